// round 8
// baseline (speedup 1.0000x reference)
#include <cuda_runtime.h>
#include <cuda_fp16.h>
#include <cstdint>
#include <cstddef>

// ---------------- problem constants ----------------
#define BATCH   4
#define SEQ     4096
#define DIM     1024
#define DINNER  1536
#define MROWS   (BATCH * SEQ)          // 16384
#define HGROW   (2 * DINNER)           // 3072 halves per hg row

#define NSEG    64
#define SEGLEN  (SEQ / NSEG)           // 64

// ---------------- static device scratch ------------
__device__ __half g_hg [(size_t)MROWS * HGROW];   // interleaved (hidden,gate)
__device__ __half g_h  [(size_t)MROWS * DINNER];
__device__ float  g_segA[BATCH * NSEG * DINNER];
__device__ float  g_segB[BATCH * NSEG * DINNER];
__device__ float  g_hin [BATCH * NSEG * DINNER];
__device__ __half g_xh [(size_t)MROWS * DIM];
__device__ __half g_whg[(size_t)HGROW * DIM];     // interleaved transposed weights
__device__ __half g_wo [DIM * DINNER];            // transposed: [DIM][DINNER]

// ---------------- helpers --------------------------
__device__ __forceinline__ void mma_f16(float& d0, float& d1, float& d2, float& d3,
                                        uint32_t a0, uint32_t a1, uint32_t a2, uint32_t a3,
                                        uint32_t b0, uint32_t b1) {
    asm volatile(
        "mma.sync.aligned.m16n8k16.row.col.f32.f16.f16.f32 "
        "{%0,%1,%2,%3},{%4,%5,%6,%7},{%8,%9},{%0,%1,%2,%3};\n"
        : "+f"(d0), "+f"(d1), "+f"(d2), "+f"(d3)
        : "r"(a0), "r"(a1), "r"(a2), "r"(a3), "r"(b0), "r"(b1));
}

__device__ __forceinline__ void ldsm4(uint32_t& r0, uint32_t& r1,
                                      uint32_t& r2, uint32_t& r3, uint32_t a) {
    asm volatile("ldmatrix.sync.aligned.m8n8.x4.shared.b16 {%0,%1,%2,%3}, [%4];"
                 : "=r"(r0), "=r"(r1), "=r"(r2), "=r"(r3) : "r"(a));
}

__device__ __forceinline__ void cp16(void* s, const void* g) {
    uint32_t sa = (uint32_t)__cvta_generic_to_shared(s);
    asm volatile("cp.async.cg.shared.global [%0], [%1], 16;\n" :: "r"(sa), "l"(g));
}
__device__ __forceinline__ void cp_commit() {
    asm volatile("cp.async.commit_group;\n");
}
template<int N> __device__ __forceinline__ void cp_wait() {
    asm volatile("cp.async.wait_group %0;\n" :: "n"(N));
}

// ---------------- convert fp32 -> fp16 ----------------
__global__ void k_cvt_h(const float4* __restrict__ in, __half2* __restrict__ out, int n4)
{
    int i = blockIdx.x * 256 + threadIdx.x;
    if (i < n4) {
        float4 v = in[i];
        out[2 * i + 0] = __floats2half2_rn(v.x, v.y);
        out[2 * i + 1] = __floats2half2_rn(v.z, v.w);
    }
}

// -------- transpose Wh,Wg [DIM][DINNER] f32 -> interleaved [2*DINNER][DIM] f16
__global__ void k_transpose_hg(const float* __restrict__ Wh, const float* __restrict__ Wg,
                               __half* __restrict__ out)
{
    __shared__ float th[32][33], tg[32][33];
    int x  = blockIdx.x * 32 + threadIdx.x;     // f
    int y0 = blockIdx.y * 32 + threadIdx.y;     // k
    #pragma unroll
    for (int i = 0; i < 32; i += 8) {
        th[threadIdx.y + i][threadIdx.x] = Wh[(size_t)(y0 + i) * DINNER + x];
        tg[threadIdx.y + i][threadIdx.x] = Wg[(size_t)(y0 + i) * DINNER + x];
    }
    __syncthreads();
    int k2 = blockIdx.y * 32 + threadIdx.x;     // k
    #pragma unroll
    for (int i = 0; i < 32; i += 8) {
        int f = blockIdx.x * 32 + threadIdx.y + i;
        out[(size_t)(2 * f + 0) * DIM + k2] = __float2half_rn(th[threadIdx.x][threadIdx.y + i]);
        out[(size_t)(2 * f + 1) * DIM + k2] = __float2half_rn(tg[threadIdx.x][threadIdx.y + i]);
    }
}

// -------- transpose fp32 [R][C] -> fp16 [C][R] (for Wo) -----------
__global__ void k_transpose_h(const float* __restrict__ in, __half* __restrict__ out,
                              int R, int C)
{
    __shared__ float t[32][33];
    int x  = blockIdx.x * 32 + threadIdx.x;
    int y0 = blockIdx.y * 32 + threadIdx.y;
    #pragma unroll
    for (int i = 0; i < 32; i += 8)
        t[threadIdx.y + i][threadIdx.x] = in[(size_t)(y0 + i) * C + x];
    __syncthreads();
    int x2 = blockIdx.y * 32 + threadIdx.x;
    #pragma unroll
    for (int i = 0; i < 32; i += 8)
        out[(size_t)(blockIdx.x * 32 + threadIdx.y + i) * R + x2] =
            __float2half_rn(t[threadIdx.x][threadIdx.y + i]);
}

// ================================================================
// Pipelined fp16 GEMM:  C[M, ND] = A[M, KD] @ B[ND, KD]^T
// BM=128, BN=256, BK=32 halves, 5-stage cp.async ring,
// two K-tiles per barrier, 256 threads (8 warps 2x4, warp tile 64x64),
// 1 CTA/SM, ldmatrix fragment loads, f32 accumulate.
// ================================================================
#define BKH     32                 // halves per K tile
#define RSTR    20                 // 32-bit words per smem row (16 payload + 4 pad)
#define ROWB    (RSTR * 4)         // 80 bytes per row
#define A_T     10240              // 128 rows * 80B
#define B_T     20480              // 256 rows * 80B
#define STG_B   (A_T + B_T)        // 30720 bytes per stage
#define STAGES  5
#define GEMM_SMEM (STAGES * STG_B) // 153600 -> 1 CTA/SM

template<int KD>
__device__ __forceinline__ void load_stage(char* smem, int s, int k0,
                                           const __half* __restrict__ A,
                                           const __half* __restrict__ B,
                                           int row0, int col0, int tid)
{
    char* sa = smem + s * STG_B;
    char* sb = sa + A_T;
    #pragma unroll
    for (int i = 0; i < 2; i++) {              // A: 512 chunks of 16B
        int id = tid + i * 256;
        int row = id >> 2, c = id & 3;
        cp16(sa + row * ROWB + c * 16, A + (size_t)(row0 + row) * KD + k0 + c * 8);
    }
    #pragma unroll
    for (int i = 0; i < 4; i++) {              // B: 1024 chunks of 16B
        int id = tid + i * 256;
        int row = id >> 2, c = id & 3;
        cp16(sb + row * ROWB + c * 16, B + (size_t)(col0 + row) * KD + k0 + c * 8);
    }
}

__device__ __forceinline__ void compute_stage(uint32_t sbase, int s,
                                              float (&acc)[4][8][4],
                                              int wm, int wn, int lane)
{
    const uint32_t sa = sbase + s * STG_B;
    const uint32_t sb = sa + A_T;
    const int arow  = lane & 15;
    const int achk  = (lane >> 4) * 16;
    const int brow  = (lane & 7) + ((lane >> 4) & 1) * 8;
    const int bchk  = ((lane >> 3) & 1) * 16;

    #pragma unroll
    for (int kk = 0; kk < 2; kk++) {           // two k16 groups, 32B apart
        uint32_t af[4][4];
        #pragma unroll
        for (int mt = 0; mt < 4; mt++) {
            uint32_t a = sa + (wm * 64 + mt * 16 + arow) * ROWB + achk + kk * 32;
            ldsm4(af[mt][0], af[mt][1], af[mt][2], af[mt][3], a);
        }
        uint32_t bf[8][2];
        #pragma unroll
        for (int p = 0; p < 4; p++) {
            uint32_t a = sb + (wn * 64 + p * 16 + brow) * ROWB + bchk + kk * 32;
            ldsm4(bf[2 * p][0], bf[2 * p][1], bf[2 * p + 1][0], bf[2 * p + 1][1], a);
        }
        #pragma unroll
        for (int mt = 0; mt < 4; mt++)
            #pragma unroll
            for (int nt = 0; nt < 8; nt++)
                mma_f16(acc[mt][nt][0], acc[mt][nt][1],
                        acc[mt][nt][2], acc[mt][nt][3],
                        af[mt][0], af[mt][1], af[mt][2], af[mt][3],
                        bf[nt][0], bf[nt][1]);
    }
}

template<int KD, int ND, typename OutT>
__global__ void __launch_bounds__(256, 1)
k_gemm(const __half* __restrict__ A, const __half* __restrict__ B,
       OutT* __restrict__ C)
{
    extern __shared__ char smem[];
    const uint32_t sbase = (uint32_t)__cvta_generic_to_shared(smem);

    const int tid  = threadIdx.x;
    const int lane = tid & 31;
    const int wid  = tid >> 5;
    const int wm   = wid & 1;     // 0..1  (M, 64 rows each)
    const int wn   = wid >> 1;    // 0..3  (N, 64 cols each)

    const int row0 = blockIdx.x * 128;
    const int col0 = blockIdx.y * 256;

    float acc[4][8][4];
    #pragma unroll
    for (int a = 0; a < 4; a++)
        #pragma unroll
        for (int b = 0; b < 8; b++)
            #pragma unroll
            for (int c = 0; c < 4; c++) acc[a][b][c] = 0.0f;

    // prologue: tiles 0,1,2 into stages 0,1,2 (one group per tile)
    #pragma unroll
    for (int s = 0; s < 3; s++) {
        load_stage<KD>(smem, s, s * BKH, A, B, row0, col0, tid);
        cp_commit();
    }

    const int KT = KD / BKH;      // 32 or 48 (always even)
    const int P  = KT / 2;

    int rs = 0;                   // stage of tile 2i
    int ws = 3;                   // stage of tile 2i+3
    for (int i = 0; i < P; i++) {
        cp_wait<1>();             // tiles 2i, 2i+1 arrived
        __syncthreads();          // visible to all; prior compute done

        int t0 = 2 * i + 3, t1 = 2 * i + 4;
        if (t0 < KT) load_stage<KD>(smem, ws, t0 * BKH, A, B, row0, col0, tid);
        cp_commit();              // unconditional: keeps group counts aligned
        int ws2 = (ws + 1 == STAGES) ? 0 : ws + 1;
        if (t1 < KT) load_stage<KD>(smem, ws2, t1 * BKH, A, B, row0, col0, tid);
        cp_commit();
        ws = (ws2 + 1 == STAGES) ? 0 : ws2 + 1;

        compute_stage(sbase, rs, acc, wm, wn, lane);
        int rs2 = (rs + 1 == STAGES) ? 0 : rs + 1;
        compute_stage(sbase, rs2, acc, wm, wn, lane);
        rs = (rs2 + 1 == STAGES) ? 0 : rs2 + 1;
    }

    // epilogue
    #pragma unroll
    for (int mt = 0; mt < 4; mt++) {
        #pragma unroll
        for (int nt = 0; nt < 8; nt++) {
            int r = row0 + wm * 64 + mt * 16 + (lane >> 2);
            int c = col0 + wn * 64 + nt * 8 + (lane & 3) * 2;
            #pragma unroll
            for (int half = 0; half < 2; half++) {
                float w0 = acc[mt][nt][half * 2 + 0];
                float w1 = acc[mt][nt][half * 2 + 1];
                size_t idx = (size_t)(r + half * 8) * ND + c;
                if constexpr (sizeof(OutT) == 2) {
                    *reinterpret_cast<__half2*>(
                        reinterpret_cast<__half*>(C) + idx) = __floats2half2_rn(w0, w1);
                } else {
                    *reinterpret_cast<float2*>(
                        reinterpret_cast<float*>(C) + idx) = make_float2(w0, w1);
                }
            }
        }
    }
}

// ================================================================
// Gating + segmented linear scan over interleaved (hidden,gate) stream
//   e = exp(gate); c = 1/(1+e); z = 1-c; v = z * g(hidden)
//   h_t = c_t * h_{t-1} + v_t
// ================================================================
__device__ __forceinline__ void gating(float hid, float gat, float& c, float& v)
{
    float e = __expf(gat);
    c = 1.0f / (1.0f + e);
    float z = 1.0f - c;
    float g = (hid >= 0.0f) ? (hid + 0.5f) : (1.0f / (1.0f + __expf(-hid)));
    v = z * g;
}

#define HGROW4 (HGROW / 8)         // 384 uint4 per hg row
#define NTH4   (DINNER / 4)        // 384 4-channel threads per (b,seg)

__global__ void k_scan1(const uint4* __restrict__ hg,
                        float* __restrict__ segA, float* __restrict__ segB)
{
    int t   = blockIdx.x * 128 + threadIdx.x;   // 0..383
    int seg = blockIdx.y;
    int b   = blockIdx.z;
    size_t base = (size_t)(b * SEQ + seg * SEGLEN) * HGROW4 + t;
    float A[4] = {1.f, 1.f, 1.f, 1.f};
    float H[4] = {0.f, 0.f, 0.f, 0.f};
    #pragma unroll 8
    for (int i = 0; i < SEGLEN; i++) {
        uint4 u = hg[base];
        const __half2* p = reinterpret_cast<const __half2*>(&u);
        #pragma unroll
        for (int j = 0; j < 4; j++) {
            float2 pv = __half22float2(p[j]);
            float c, v;
            gating(pv.x, pv.y, c, v);
            A[j] *= c;
            H[j] = fmaf(c, H[j], v);
        }
        base += HGROW4;
    }
    int sidx = (b * NSEG + seg) * DINNER + t * 4;
    *reinterpret_cast<float4*>(segA + sidx) = make_float4(A[0], A[1], A[2], A[3]);
    *reinterpret_cast<float4*>(segB + sidx) = make_float4(H[0], H[1], H[2], H[3]);
}

__global__ void k_scan2(const float* __restrict__ segA, const float* __restrict__ segB,
                        float* __restrict__ hin)
{
    int idx = blockIdx.x * 256 + threadIdx.x;
    int b = idx / DINNER;
    int f = idx - b * DINNER;
    float h = 0.0f;
    #pragma unroll
    for (int seg = 0; seg < NSEG; seg++) {
        int sidx = (b * NSEG + seg) * DINNER + f;
        hin[sidx] = h;
        h = fmaf(segA[sidx], h, segB[sidx]);
    }
}

__global__ void k_scan3(const uint4* __restrict__ hg, const float* __restrict__ hin,
                        uint2* __restrict__ hout)
{
    int t   = blockIdx.x * 128 + threadIdx.x;   // 0..383
    int seg = blockIdx.y;
    int b   = blockIdx.z;
    size_t base = (size_t)(b * SEQ + seg * SEGLEN) * HGROW4 + t;
    size_t obase = (size_t)(b * SEQ + seg * SEGLEN) * (DINNER / 4) + t;
    float4 h0 = *reinterpret_cast<const float4*>(
        hin + (b * NSEG + seg) * DINNER + t * 4);
    float H[4] = {h0.x, h0.y, h0.z, h0.w};
    #pragma unroll 8
    for (int i = 0; i < SEGLEN; i++) {
        uint4 u = hg[base];
        const __half2* p = reinterpret_cast<const __half2*>(&u);
        __half2 o[2];
        #pragma unroll
        for (int j = 0; j < 4; j++) {
            float2 pv = __half22float2(p[j]);
            float c, v;
            gating(pv.x, pv.y, c, v);
            H[j] = fmaf(c, H[j], v);
        }
        o[0] = __floats2half2_rn(H[0], H[1]);
        o[1] = __floats2half2_rn(H[2], H[3]);
        uint2 w;
        w.x = *reinterpret_cast<uint32_t*>(&o[0]);
        w.y = *reinterpret_cast<uint32_t*>(&o[1]);
        hout[obase] = w;
        base += HGROW4;
        obase += DINNER / 4;
    }
}

// ================================================================
// launch
// ================================================================
extern "C" void kernel_launch(void* const* d_in, const int* in_sizes, int n_in,
                              void* d_out, int out_size)
{
    const float* x  = (const float*)d_in[0];
    const float* Wh = (const float*)d_in[1];
    const float* Wg = (const float*)d_in[2];
    const float* Wo = (const float*)d_in[3];
    float* out = (float*)d_out;

    __half *hgp, *h, *xh, *whg, *wo;
    float *sa, *sb, *hin;
    cudaGetSymbolAddress((void**)&hgp, g_hg);
    cudaGetSymbolAddress((void**)&h,   g_h);
    cudaGetSymbolAddress((void**)&sa,  g_segA);
    cudaGetSymbolAddress((void**)&sb,  g_segB);
    cudaGetSymbolAddress((void**)&hin, g_hin);
    cudaGetSymbolAddress((void**)&xh,  g_xh);
    cudaGetSymbolAddress((void**)&whg, g_whg);
    cudaGetSymbolAddress((void**)&wo,  g_wo);

    cudaFuncSetAttribute(k_gemm<DIM, HGROW, __half>,
                         cudaFuncAttributeMaxDynamicSharedMemorySize, GEMM_SMEM);
    cudaFuncSetAttribute(k_gemm<DINNER, DIM, float>,
                         cudaFuncAttributeMaxDynamicSharedMemorySize, GEMM_SMEM);

    // 1. convert x to fp16; build interleaved W_hg and transposed W_o
    {
        int n4 = (int)((size_t)MROWS * DIM / 4);
        k_cvt_h<<<(n4 + 255) / 256, 256>>>((const float4*)x, (__half2*)xh, n4);
        dim3 tb(32, 8);
        k_transpose_hg<<<dim3(DINNER / 32, DIM / 32), tb>>>(Wh, Wg, whg);
        k_transpose_h<<<dim3(DIM / 32, DINNER / 32), tb>>>(Wo, wo, DINNER, DIM);
    }

    // 2. fused dual projection: hg = x @ [Wh|Wg] (interleaved cols)
    dim3 gP(MROWS / 128, HGROW / 256);        // 128 x 12
    k_gemm<DIM, HGROW, __half><<<gP, 256, GEMM_SMEM>>>(xh, whg, hgp);

    // 3. segmented scan (gating fused)
    dim3 gS(NTH4 / 128, NSEG, BATCH);         // 3 x 64 x 4
    k_scan1<<<gS, 128>>>((const uint4*)hgp, sa, sb);
    k_scan2<<<(BATCH * DINNER) / 256, 256>>>(sa, sb, hin);
    k_scan3<<<gS, 128>>>((const uint4*)hgp, hin, (uint2*)h);

    // 4. output projection
    dim3 gO(MROWS / 128, DIM / 256);          // 128 x 4
    k_gemm<DINNER, DIM, float><<<gO, 256, GEMM_SMEM>>>(h, wo, out);
}